// round 1
// baseline (speedup 1.0000x reference)
#include <cuda_runtime.h>
#include <math.h>

#define B_   2
#define SQ_  1024
#define SKV_ 2048
#define E_   1024
#define H_   16
#define D_   64
#define VOC_ 4096

// Scratch (static __device__ arrays — no allocation in kernel_launch)
__device__ float g_Q [B_*SQ_ *E_];   // Q projection  [B*SQ,  E]
__device__ float g_K [B_*SKV_*E_];   // K projection  [B*SKV, E]
__device__ float g_V [B_*SKV_*E_];   // V projection  [B*SKV, E]
__device__ float g_AO[B_*SQ_ *E_];   // attention out [B*SQ,  E]

// ---------------------------------------------------------------------------
// Generic SGEMM: C[M,N] = A[M,K] @ W[K,N] + bias[N]
// BM=BN=128, BK=8, 256 threads, 8x8 microtile per thread.
// All problem dims are multiples of the tile sizes -> no bounds checks.
// ---------------------------------------------------------------------------
__global__ __launch_bounds__(256, 2)
void sgemm_bias(const float* __restrict__ A, const float* __restrict__ W,
                const float* __restrict__ bias, float* __restrict__ C,
                int M, int N, int K)
{
    __shared__ float As[8][128];   // [k][m]  (A tile stored transposed)
    __shared__ float Bs[8][128];   // [k][n]

    const int tid = threadIdx.x;
    const int rowBase = blockIdx.y * 128;
    const int colBase = blockIdx.x * 128;

    // A-tile load mapping: 128 rows x 8 cols = 256 float4 (2 per row)
    const int aRow  = tid >> 1;
    const int aCol4 = (tid & 1) << 2;
    // W-tile load mapping: 8 rows x 128 cols = 256 float4 (32 per row)
    const int bRow  = tid >> 5;
    const int bCol4 = (tid & 31) << 2;

    const int ty = tid >> 4;       // 0..15 -> 8 output rows each
    const int tx = tid & 15;       // 0..15 -> 8 output cols each

    float acc[8][8];
#pragma unroll
    for (int i = 0; i < 8; i++)
#pragma unroll
        for (int j = 0; j < 8; j++) acc[i][j] = 0.f;

    for (int k0 = 0; k0 < K; k0 += 8) {
        float4 av = *(const float4*)(A + (size_t)(rowBase + aRow) * K + k0 + aCol4);
        As[aCol4 + 0][aRow] = av.x;
        As[aCol4 + 1][aRow] = av.y;
        As[aCol4 + 2][aRow] = av.z;
        As[aCol4 + 3][aRow] = av.w;
        *(float4*)&Bs[bRow][bCol4] =
            *(const float4*)(W + (size_t)(k0 + bRow) * N + colBase + bCol4);
        __syncthreads();

#pragma unroll
        for (int kk = 0; kk < 8; kk++) {
            float ra[8], rb[8];
            *(float4*)&ra[0] = *(const float4*)&As[kk][ty * 8];
            *(float4*)&ra[4] = *(const float4*)&As[kk][ty * 8 + 4];
            *(float4*)&rb[0] = *(const float4*)&Bs[kk][tx * 8];
            *(float4*)&rb[4] = *(const float4*)&Bs[kk][tx * 8 + 4];
#pragma unroll
            for (int i = 0; i < 8; i++)
#pragma unroll
                for (int j = 0; j < 8; j++)
                    acc[i][j] += ra[i] * rb[j];
        }
        __syncthreads();
    }

    // Epilogue: add bias, store
#pragma unroll
    for (int i = 0; i < 8; i++) {
        const size_t r = (size_t)(rowBase + ty * 8 + i) * N;
#pragma unroll
        for (int j = 0; j < 8; j += 4) {
            const int c = colBase + tx * 8 + j;
            float4 bv = *(const float4*)(bias + c);
            float4 o;
            o.x = acc[i][j + 0] + bv.x;
            o.y = acc[i][j + 1] + bv.y;
            o.z = acc[i][j + 2] + bv.z;
            o.w = acc[i][j + 3] + bv.w;
            *(float4*)(C + r + c) = o;
        }
    }
}

// ---------------------------------------------------------------------------
// Flash attention: one CTA = (batch b, head h, 64-query tile).
// smem: Qs [d][q] 16KB, KVs (K phase [d][kv], V phase [kv][d]) 16KB,
//       Ps [kv][q] 16KB -> exactly 48KB static.
// Thread (ty,tx): q rows ty*4..+3, kv/d cols tx*4..+3. Online softmax with
// row reductions over the 16 tx lanes (shfl_xor 1/2/4/8 stays in-warp).
// ---------------------------------------------------------------------------
__global__ __launch_bounds__(256)
void attn_kernel(const float* __restrict__ Q, const float* __restrict__ K,
                 const float* __restrict__ V, float* __restrict__ O)
{
    __shared__ float Qs [64][64];
    __shared__ float KVs[64][64];
    __shared__ float Ps [64][64];

    const int tid = threadIdx.x;
    const int ty = tid >> 4, tx = tid & 15;
    const int qt = blockIdx.x, h = blockIdx.y, b = blockIdx.z;
    const float scale = 0.125f;   // 1/sqrt(64)

    const size_t qbase = ((size_t)(b * SQ_ + qt * 64)) * E_ + h * D_;

    // Load Q tile transposed: Qs[d][q]
#pragma unroll
    for (int i = 0; i < 4; i++) {
        int idx = tid + i * 256;
        int q = idx >> 4;
        int d4 = (idx & 15) << 2;
        float4 v = *(const float4*)(Q + qbase + (size_t)q * E_ + d4);
        Qs[d4 + 0][q] = v.x; Qs[d4 + 1][q] = v.y;
        Qs[d4 + 2][q] = v.z; Qs[d4 + 3][q] = v.w;
    }

    float m[4], l[4], o[4][4];
#pragma unroll
    for (int r = 0; r < 4; r++) {
        m[r] = -1e30f; l[r] = 0.f;
#pragma unroll
        for (int c = 0; c < 4; c++) o[r][c] = 0.f;
    }

    for (int kvt = 0; kvt < SKV_ / 64; kvt++) {
        const size_t kbase = ((size_t)(b * SKV_ + kvt * 64)) * E_ + h * D_;

        __syncthreads();   // previous PV phase done (also orders Qs on iter 0)
        // Load K tile transposed: KVs[d][kv]
#pragma unroll
        for (int i = 0; i < 4; i++) {
            int idx = tid + i * 256;
            int kv = idx >> 4;
            int d4 = (idx & 15) << 2;
            float4 v = *(const float4*)(K + kbase + (size_t)kv * E_ + d4);
            KVs[d4 + 0][kv] = v.x; KVs[d4 + 1][kv] = v.y;
            KVs[d4 + 2][kv] = v.z; KVs[d4 + 3][kv] = v.w;
        }
        __syncthreads();

        // S = Q K^T for this thread's 4x4 microtile
        float s[4][4];
#pragma unroll
        for (int r = 0; r < 4; r++)
#pragma unroll
            for (int c = 0; c < 4; c++) s[r][c] = 0.f;

#pragma unroll 8
        for (int d = 0; d < 64; d++) {
            float4 qv = *(const float4*)&Qs[d][ty << 2];
            float4 kk = *(const float4*)&KVs[d][tx << 2];
            const float qa[4] = {qv.x, qv.y, qv.z, qv.w};
            const float ka[4] = {kk.x, kk.y, kk.z, kk.w};
#pragma unroll
            for (int r = 0; r < 4; r++)
#pragma unroll
                for (int c = 0; c < 4; c++)
                    s[r][c] += qa[r] * ka[c];
        }

        // Online softmax update
        float p[4][4];
#pragma unroll
        for (int r = 0; r < 4; r++) {
#pragma unroll
            for (int c = 0; c < 4; c++) s[r][c] *= scale;
            float rm = fmaxf(fmaxf(s[r][0], s[r][1]), fmaxf(s[r][2], s[r][3]));
            rm = fmaxf(rm, __shfl_xor_sync(0xffffffffu, rm, 1));
            rm = fmaxf(rm, __shfl_xor_sync(0xffffffffu, rm, 2));
            rm = fmaxf(rm, __shfl_xor_sync(0xffffffffu, rm, 4));
            rm = fmaxf(rm, __shfl_xor_sync(0xffffffffu, rm, 8));
            float mn = fmaxf(m[r], rm);
            float al = __expf(m[r] - mn);
            float rs = 0.f;
#pragma unroll
            for (int c = 0; c < 4; c++) {
                p[r][c] = __expf(s[r][c] - mn);
                rs += p[r][c];
            }
            rs += __shfl_xor_sync(0xffffffffu, rs, 1);
            rs += __shfl_xor_sync(0xffffffffu, rs, 2);
            rs += __shfl_xor_sync(0xffffffffu, rs, 4);
            rs += __shfl_xor_sync(0xffffffffu, rs, 8);
            l[r] = l[r] * al + rs;
            m[r] = mn;
#pragma unroll
            for (int c = 0; c < 4; c++) o[r][c] *= al;
        }

        // Write P transposed: Ps[kv][q]
#pragma unroll
        for (int c = 0; c < 4; c++) {
            float4 pv = make_float4(p[0][c], p[1][c], p[2][c], p[3][c]);
            *(float4*)&Ps[(tx << 2) + c][ty << 2] = pv;
        }
        __syncthreads();   // Ps complete; all S reads of KVs done

        // Load V tile: KVs[kv][d] (overwrites K)
#pragma unroll
        for (int i = 0; i < 4; i++) {
            int idx = tid + i * 256;
            int kv = idx >> 4;
            int d4 = (idx & 15) << 2;
            *(float4*)&KVs[kv][d4] =
                *(const float4*)(V + kbase + (size_t)kv * E_ + d4);
        }
        __syncthreads();

        // O += P @ V
#pragma unroll 8
        for (int kv = 0; kv < 64; kv++) {
            float4 pv = *(const float4*)&Ps[kv][ty << 2];
            float4 vv = *(const float4*)&KVs[kv][tx << 2];
            const float pa[4] = {pv.x, pv.y, pv.z, pv.w};
            const float va[4] = {vv.x, vv.y, vv.z, vv.w};
#pragma unroll
            for (int r = 0; r < 4; r++)
#pragma unroll
                for (int c = 0; c < 4; c++)
                    o[r][c] += pa[r] * va[c];
        }
    }

    // Epilogue: normalize by l, store to [B*SQ, E] at head h's columns
#pragma unroll
    for (int r = 0; r < 4; r++) {
        float inv = 1.0f / l[r];
        size_t row = (size_t)(b * SQ_ + qt * 64 + (ty << 2) + r) * E_
                     + h * D_ + (tx << 2);
        float4 ov = make_float4(o[r][0] * inv, o[r][1] * inv,
                                o[r][2] * inv, o[r][3] * inv);
        *(float4*)(O + row) = ov;
    }
}

// ---------------------------------------------------------------------------
// Launch
// ---------------------------------------------------------------------------
extern "C" void kernel_launch(void* const* d_in, const int* in_sizes, int n_in,
                              void* d_out, int out_size)
{
    (void)in_sizes; (void)n_in; (void)out_size;
    const float* x   = (const float*)d_in[0];
    const float* ctx = (const float*)d_in[1];
    const float* Wq  = (const float*)d_in[2];
    const float* bq  = (const float*)d_in[3];
    const float* Wk  = (const float*)d_in[4];
    const float* bk  = (const float*)d_in[5];
    const float* Wv  = (const float*)d_in[6];
    const float* bv  = (const float*)d_in[7];
    const float* Wp  = (const float*)d_in[8];
    const float* bp  = (const float*)d_in[9];
    float* out = (float*)d_out;

    float *Qd, *Kd, *Vd, *AOd;
    cudaGetSymbolAddress((void**)&Qd,  g_Q);
    cudaGetSymbolAddress((void**)&Kd,  g_K);
    cudaGetSymbolAddress((void**)&Vd,  g_V);
    cudaGetSymbolAddress((void**)&AOd, g_AO);

    // Q/K/V projections
    sgemm_bias<<<dim3(E_ / 128, (B_ * SQ_) / 128),  256>>>(x,   Wq, bq, Qd, B_ * SQ_,  E_, E_);
    sgemm_bias<<<dim3(E_ / 128, (B_ * SKV_) / 128), 256>>>(ctx, Wk, bk, Kd, B_ * SKV_, E_, E_);
    sgemm_bias<<<dim3(E_ / 128, (B_ * SKV_) / 128), 256>>>(ctx, Wv, bv, Vd, B_ * SKV_, E_, E_);

    // Attention
    attn_kernel<<<dim3(SQ_ / 64, H_, B_), 256>>>(Qd, Kd, Vd, AOd);

    // Vocab projection
    sgemm_bias<<<dim3(VOC_ / 128, (B_ * SQ_) / 128), 256>>>(AOd, Wp, bp, out, B_ * SQ_, VOC_, E_);
}

// round 5
// speedup vs baseline: 6.0714x; 6.0714x over previous
#include <cuda_runtime.h>
#include <cuda_fp16.h>
#include <cstdint>

#define B_   2
#define SQ_  1024
#define SKV_ 2048
#define E_   1024
#define H_   16
#define VOC_ 4096
#define KDIM 1024

// ---------------------------------------------------------------------------
// Static scratch
// ---------------------------------------------------------------------------
__device__ __half g_Qh [B_*SQ_ *E_];
__device__ __half g_Kh [B_*SKV_*E_];
__device__ __half g_Vh [B_*SKV_*E_];
__device__ __half g_AOh[B_*SQ_ *E_];
__device__ __half g_xh [B_*SQ_ *E_];
__device__ __half g_ch [B_*SKV_*E_];
__device__ __half g_WqT[E_*E_];
__device__ __half g_WkT[E_*E_];
__device__ __half g_WvT[E_*E_];
__device__ __half g_WpT[(size_t)E_*VOC_];

// ---------------------------------------------------------------------------
// PTX helpers (baseline PTX only — compiles for compute_103)
// ---------------------------------------------------------------------------
__device__ __forceinline__ uint32_t smem_u32(const void* p) {
    uint32_t a;
    asm("{ .reg .u64 t; cvta.to.shared.u64 t, %1; cvt.u32.u64 %0, t; }"
        : "=r"(a) : "l"(p));
    return a;
}

#define CP16(s, g) \
    asm volatile("cp.async.cg.shared.global [%0], [%1], 16;" :: "r"(s), "l"(g))
#define CP_COMMIT() asm volatile("cp.async.commit_group;" ::: "memory")
#define CP_WAIT0()  asm volatile("cp.async.wait_group 0;" ::: "memory")
#define CP_WAIT1()  asm volatile("cp.async.wait_group 1;" ::: "memory")

#define LDSM4(d0, d1, d2, d3, a)                                              \
    asm volatile("ldmatrix.sync.aligned.m8n8.x4.shared.b16 {%0,%1,%2,%3}, [%4];" \
        : "=r"(d0), "=r"(d1), "=r"(d2), "=r"(d3) : "r"(a))
#define LDSM4T(d0, d1, d2, d3, a)                                             \
    asm volatile("ldmatrix.sync.aligned.m8n8.x4.trans.shared.b16 {%0,%1,%2,%3}, [%4];" \
        : "=r"(d0), "=r"(d1), "=r"(d2), "=r"(d3) : "r"(a))

#define MMA16816(c, a, b0, b1)                                                \
    asm volatile("mma.sync.aligned.m16n8k16.row.col.f32.f16.f16.f32 "         \
        "{%0,%1,%2,%3},{%4,%5,%6,%7},{%8,%9},{%0,%1,%2,%3};"                  \
        : "+f"((c)[0]), "+f"((c)[1]), "+f"((c)[2]), "+f"((c)[3])              \
        : "r"((a)[0]), "r"((a)[1]), "r"((a)[2]), "r"((a)[3]), "r"(b0), "r"(b1))

__device__ __forceinline__ uint32_t packh2(float x, float y) {
    __half2 h = __floats2half2_rn(x, y);
    return *reinterpret_cast<uint32_t*>(&h);
}

// ---------------------------------------------------------------------------
// Conversion kernels
// ---------------------------------------------------------------------------
__global__ void f2h_kernel(const float* __restrict__ in,
                           __half* __restrict__ out, int n)
{
    int i = (blockIdx.x * blockDim.x + threadIdx.x) * 4;
    if (i >= n) return;
    float4 v = *(const float4*)(in + i);
    *(__half2*)(out + i)     = __floats2half2_rn(v.x, v.y);
    *(__half2*)(out + i + 2) = __floats2half2_rn(v.z, v.w);
}

// W[K][N] fp32 -> Wt[N][K] fp16
__global__ void f2hT_kernel(const float* __restrict__ W,
                            __half* __restrict__ Wt, int K, int N)
{
    __shared__ float t[32][33];
    int k0 = blockIdx.y * 32, n0 = blockIdx.x * 32;
    int tx = threadIdx.x, ty = threadIdx.y;
#pragma unroll
    for (int i = ty; i < 32; i += 8)
        t[i][tx] = W[(size_t)(k0 + i) * N + n0 + tx];
    __syncthreads();
#pragma unroll
    for (int i = ty; i < 32; i += 8)
        Wt[(size_t)(n0 + i) * K + k0 + tx] = __float2half(t[tx][i]);
}

// ---------------------------------------------------------------------------
// fp16 tensor-core GEMM: C[M,N] = A[M,K] @ Bt[N,K]^T + bias
// 128x128x32 tiles, 256 threads, double-buffered cp.async, padded smem rows.
// Cf != nullptr -> fp32 out; else fp16 to Ch.
// ---------------------------------------------------------------------------
#define GS 40   // smem row stride in halves (32 data + 8 pad = 80B)

__global__ __launch_bounds__(256)
void gemm_h(const __half* __restrict__ A, const __half* __restrict__ Bt,
            const float* __restrict__ bias, float* __restrict__ Cf,
            __half* __restrict__ Ch, int N, int K)
{
    __shared__ __align__(16) __half As[2][128 * GS];
    __shared__ __align__(16) __half Bs[2][128 * GS];

    const int tid = threadIdx.x;
    const int lane = tid & 31, wid = tid >> 5;
    const int wm = wid & 3, wn = wid >> 2;             // 4x2 warp grid
    const int rowBase = blockIdx.y * 128, colBase = blockIdx.x * 128;

    // Tile loader: 128 rows x 4 segs (16B) = 512 chunks, 2 per thread.
    const __half* Aga[2]; const __half* Bga[2];
    uint32_t sAa[2], sBa[2];
#pragma unroll
    for (int i = 0; i < 2; i++) {
        const int idx = tid + i * 256;
        const int row = idx >> 2, seg = idx & 3;
        Aga[i] = A  + (size_t)(rowBase + row) * K + seg * 8;
        Bga[i] = Bt + (size_t)(colBase + row) * K + seg * 8;
        sAa[i] = smem_u32(&As[0][row * GS + seg * 8]);
        sBa[i] = smem_u32(&Bs[0][row * GS + seg * 8]);
    }
    const uint32_t STG = 128 * GS * 2;                  // stage bytes

    const uint32_t aAddr = smem_u32(&As[0][(wm * 32 + (lane & 15)) * GS + (lane >> 4) * 8]);
    const uint32_t bAddr = smem_u32(&Bs[0][(wn * 64 + (lane & 15)) * GS + (lane >> 4) * 8]);

    float acc[2][8][4];
#pragma unroll
    for (int i = 0; i < 2; i++)
#pragma unroll
        for (int j = 0; j < 8; j++)
#pragma unroll
            for (int q = 0; q < 4; q++) acc[i][j][q] = 0.f;

#pragma unroll
    for (int i = 0; i < 2; i++) { CP16(sAa[i], Aga[i]); CP16(sBa[i], Bga[i]); }
    CP_COMMIT();

    const int NIT = K >> 5;
    for (int it = 0; it < NIT; it++) {
        if (it + 1 < NIT) {
            const int kk = (it + 1) << 5;
            const uint32_t so = ((it + 1) & 1) * STG;
#pragma unroll
            for (int i = 0; i < 2; i++) {
                CP16(sAa[i] + so, Aga[i] + kk);
                CP16(sBa[i] + so, Bga[i] + kk);
            }
            CP_COMMIT();
            CP_WAIT1();
        } else {
            CP_WAIT0();
        }
        __syncthreads();
        const uint32_t so = (it & 1) * STG;

#pragma unroll
        for (int ks = 0; ks < 2; ks++) {
            uint32_t a[2][4];
#pragma unroll
            for (int mt = 0; mt < 2; mt++)
                LDSM4(a[mt][0], a[mt][1], a[mt][2], a[mt][3],
                      aAddr + so + (mt * 16 * GS + ks * 16) * 2);
#pragma unroll
            for (int np = 0; np < 4; np++) {
                uint32_t d0, d1, d2, d3;
                LDSM4(d0, d1, d2, d3, bAddr + so + (np * 16 * GS + ks * 16) * 2);
#pragma unroll
                for (int mt = 0; mt < 2; mt++) {
                    MMA16816(acc[mt][np * 2],     a[mt], d0, d2);
                    MMA16816(acc[mt][np * 2 + 1], a[mt], d1, d3);
                }
            }
        }
        __syncthreads();
    }

    // epilogue
    const int r0 = rowBase + wm * 32 + (lane >> 2);
    const int c0 = colBase + wn * 64 + (lane & 3) * 2;
#pragma unroll
    for (int mt = 0; mt < 2; mt++)
#pragma unroll
        for (int nt = 0; nt < 8; nt++) {
            const int c = c0 + nt * 8;
            const float bx = bias[c], by = bias[c + 1];
#pragma unroll
            for (int rr = 0; rr < 2; rr++) {
                const int r = r0 + mt * 16 + rr * 8;
                const float vx = acc[mt][nt][rr * 2]     + bx;
                const float vy = acc[mt][nt][rr * 2 + 1] + by;
                if (Cf) {
                    float2 o; o.x = vx; o.y = vy;
                    *(float2*)(Cf + (size_t)r * N + c) = o;
                } else {
                    *(__half2*)(Ch + (size_t)r * N + c) = __floats2half2_rn(vx, vy);
                }
            }
        }
}

// ---------------------------------------------------------------------------
// fp16 flash attention: CTA = (128-query tile, head, batch), 256 thr / 8 warps.
// Each warp owns 16 q rows. S = Q@K^T via mma, online softmax (base-2) in fp32
// regs, P packed to fp16 A-fragments in-register, PV via mma with V ldmatrix.trans.
// smem: Qs[128][72] + double-buffered Ks/Vs[64][72]  (55296 B dynamic).
// ---------------------------------------------------------------------------
#define AS 72   // attention smem row stride in halves (64 + 8 pad = 144B)
#define ATTN_SMEM ((128 * AS + 4 * 64 * AS) * 2)

__global__ __launch_bounds__(256)
void attn_h(const __half* __restrict__ Q, const __half* __restrict__ K,
            const __half* __restrict__ V, __half* __restrict__ O)
{
    extern __shared__ __align__(16) __half sh[];
    __half* Qs = sh;                       // 128*72
    __half* Ks = sh + 128 * AS;            // 2 stages of 64*72
    __half* Vs = Ks + 2 * 64 * AS;

    const int tid = threadIdx.x, lane = tid & 31, wid = tid >> 5;
    const int qt = blockIdx.x, h = blockIdx.y, b = blockIdx.z;

    const __half* Qg = Q + ((size_t)b * SQ_ + qt * 128) * E_ + h * 64;
#pragma unroll
    for (int i = 0; i < 4; i++) {
        int idx = tid + i * 256;           // 0..1023
        int row = idx >> 3, seg = idx & 7;
        *(uint4*)(Qs + row * AS + seg * 8) =
            *(const uint4*)(Qg + (size_t)row * E_ + seg * 8);
    }

    const __half* Kg0 = K + (size_t)b * SKV_ * E_ + h * 64;
    const __half* Vg0 = V + (size_t)b * SKV_ * E_ + h * 64;
    const uint32_t ksb = smem_u32(Ks), vsb = smem_u32(Vs);
    const uint32_t KSTG = 64 * AS * 2;

    auto issue = [&](int st, int c) {
        const __half* Kg = Kg0 + (size_t)c * 64 * E_;
        const __half* Vg = Vg0 + (size_t)c * 64 * E_;
#pragma unroll
        for (int i = 0; i < 2; i++) {
            int idx = tid + i * 256;       // 0..511
            int row = idx >> 3, seg = idx & 7;
            uint32_t so = st * KSTG + (row * AS + seg * 8) * 2;
            CP16(ksb + so, Kg + (size_t)row * E_ + seg * 8);
            CP16(vsb + so, Vg + (size_t)row * E_ + seg * 8);
        }
        CP_COMMIT();
    };

    issue(0, 0);

    float m2[2] = { -1e30f, -1e30f };
    float ls[2] = { 0.f, 0.f };
    float o[8][4];
#pragma unroll
    for (int i = 0; i < 8; i++)
#pragma unroll
        for (int j = 0; j < 4; j++) o[i][j] = 0.f;

    const uint32_t qAddr = smem_u32(Qs + (wid * 16 + (lane & 15)) * AS + (lane >> 4) * 8);
    const float c2 = 0.125f * 1.44269504089f;   // scale * log2(e)

    for (int c = 0; c < SKV_ / 64; c++) {
        if (c + 1 < SKV_ / 64) { issue((c + 1) & 1, c + 1); CP_WAIT1(); }
        else                   { CP_WAIT0(); }
        __syncthreads();
        const uint32_t so = (c & 1) * KSTG;

        // ---- S = Q @ K^T  (16 x 64 per warp)
        float sacc[8][4];
#pragma unroll
        for (int i = 0; i < 8; i++)
#pragma unroll
            for (int j = 0; j < 4; j++) sacc[i][j] = 0.f;

#pragma unroll
        for (int ks = 0; ks < 4; ks++) {
            uint32_t a[4];
            LDSM4(a[0], a[1], a[2], a[3], qAddr + ks * 32);
#pragma unroll
            for (int np = 0; np < 4; np++) {
                uint32_t d0, d1, d2, d3;
                LDSM4(d0, d1, d2, d3,
                      ksb + so + ((np * 16 + (lane & 15)) * AS + ks * 16 + (lane >> 4) * 8) * 2);
                MMA16816(sacc[np * 2],     a, d0, d2);
                MMA16816(sacc[np * 2 + 1], a, d1, d3);
            }
        }

        // ---- online softmax (base-2)
#pragma unroll
        for (int i = 0; i < 8; i++)
#pragma unroll
            for (int j = 0; j < 4; j++) sacc[i][j] *= c2;

#pragma unroll
        for (int rr = 0; rr < 2; rr++) {
            float mx = -1e30f;
#pragma unroll
            for (int nt = 0; nt < 8; nt++)
                mx = fmaxf(mx, fmaxf(sacc[nt][rr * 2], sacc[nt][rr * 2 + 1]));
            mx = fmaxf(mx, __shfl_xor_sync(0xffffffffu, mx, 1));
            mx = fmaxf(mx, __shfl_xor_sync(0xffffffffu, mx, 2));
            const float mn = fmaxf(m2[rr], mx);
            const float al = exp2f(m2[rr] - mn);
            float rs = 0.f;
#pragma unroll
            for (int nt = 0; nt < 8; nt++) {
                sacc[nt][rr * 2]     = exp2f(sacc[nt][rr * 2]     - mn);
                sacc[nt][rr * 2 + 1] = exp2f(sacc[nt][rr * 2 + 1] - mn);
                rs += sacc[nt][rr * 2] + sacc[nt][rr * 2 + 1];
            }
            rs += __shfl_xor_sync(0xffffffffu, rs, 1);
            rs += __shfl_xor_sync(0xffffffffu, rs, 2);
            ls[rr] = ls[rr] * al + rs;
            m2[rr] = mn;
#pragma unroll
            for (int nt = 0; nt < 8; nt++) {
                o[nt][rr * 2]     *= al;
                o[nt][rr * 2 + 1] *= al;
            }
        }

        // ---- O += P @ V  (P fragments built in-register from sacc)
        const int g = lane >> 3;
#pragma unroll
        for (int t = 0; t < 4; t++) {
            uint32_t pa[4];
            pa[0] = packh2(sacc[2 * t][0],     sacc[2 * t][1]);
            pa[1] = packh2(sacc[2 * t][2],     sacc[2 * t][3]);
            pa[2] = packh2(sacc[2 * t + 1][0], sacc[2 * t + 1][1]);
            pa[3] = packh2(sacc[2 * t + 1][2], sacc[2 * t + 1][3]);
#pragma unroll
            for (int np = 0; np < 4; np++) {
                uint32_t d0, d1, d2, d3;
                uint32_t va = vsb + so +
                    ((t * 16 + (g & 1) * 8 + (lane & 7)) * AS + np * 16 + (g >> 1) * 8) * 2;
                LDSM4T(d0, d1, d2, d3, va);
                MMA16816(o[np * 2],     pa, d0, d1);
                MMA16816(o[np * 2 + 1], pa, d2, d3);
            }
        }
        __syncthreads();
    }

    // ---- epilogue: normalize, fp16 store
#pragma unroll
    for (int rr = 0; rr < 2; rr++) {
        const float inv = 1.f / ls[rr];
        const int row = qt * 128 + wid * 16 + (lane >> 2) + rr * 8;
        const size_t base = ((size_t)b * SQ_ + row) * E_ + h * 64 + (lane & 3) * 2;
#pragma unroll
        for (int nt = 0; nt < 8; nt++)
            *(__half2*)(O + base + nt * 8) =
                __floats2half2_rn(o[nt][rr * 2] * inv, o[nt][rr * 2 + 1] * inv);
    }
}

// ---------------------------------------------------------------------------
// Launch
// ---------------------------------------------------------------------------
extern "C" void kernel_launch(void* const* d_in, const int* in_sizes, int n_in,
                              void* d_out, int out_size)
{
    (void)in_sizes; (void)n_in; (void)out_size;
    const float* x   = (const float*)d_in[0];
    const float* ctx = (const float*)d_in[1];
    const float* Wq  = (const float*)d_in[2];
    const float* bq  = (const float*)d_in[3];
    const float* Wk  = (const float*)d_in[4];
    const float* bk  = (const float*)d_in[5];
    const float* Wv  = (const float*)d_in[6];
    const float* bv  = (const float*)d_in[7];
    const float* Wp  = (const float*)d_in[8];
    const float* bp  = (const float*)d_in[9];
    float* out = (float*)d_out;

    __half *Qh, *Kh, *Vh, *AOh, *xh, *ch, *wq, *wk, *wv, *wp;
    cudaGetSymbolAddress((void**)&Qh,  g_Qh);
    cudaGetSymbolAddress((void**)&Kh,  g_Kh);
    cudaGetSymbolAddress((void**)&Vh,  g_Vh);
    cudaGetSymbolAddress((void**)&AOh, g_AOh);
    cudaGetSymbolAddress((void**)&xh,  g_xh);
    cudaGetSymbolAddress((void**)&ch,  g_ch);
    cudaGetSymbolAddress((void**)&wq,  g_WqT);
    cudaGetSymbolAddress((void**)&wk,  g_WkT);
    cudaGetSymbolAddress((void**)&wv,  g_WvT);
    cudaGetSymbolAddress((void**)&wp,  g_WpT);

    cudaFuncSetAttribute(attn_h, cudaFuncAttributeMaxDynamicSharedMemorySize, ATTN_SMEM);

    // fp32 -> fp16 conversions
    {
        int n = B_ * SQ_ * E_;
        f2h_kernel<<<n / 4 / 256, 256>>>(x, xh, n);
    }
    {
        int n = B_ * SKV_ * E_;
        f2h_kernel<<<n / 4 / 256, 256>>>(ctx, ch, n);
    }
    f2hT_kernel<<<dim3(E_ / 32,   E_ / 32), dim3(32, 8)>>>(Wq, wq, E_, E_);
    f2hT_kernel<<<dim3(E_ / 32,   E_ / 32), dim3(32, 8)>>>(Wk, wk, E_, E_);
    f2hT_kernel<<<dim3(E_ / 32,   E_ / 32), dim3(32, 8)>>>(Wv, wv, E_, E_);
    f2hT_kernel<<<dim3(VOC_ / 32, E_ / 32), dim3(32, 8)>>>(Wp, wp, E_, VOC_);

    // QKV projections (fp16 out)
    gemm_h<<<dim3(E_ / 128, (B_ * SQ_)  / 128), 256>>>(xh, wq, bq, nullptr, Qh, E_, KDIM);
    gemm_h<<<dim3(E_ / 128, (B_ * SKV_) / 128), 256>>>(ch, wk, bk, nullptr, Kh, E_, KDIM);
    gemm_h<<<dim3(E_ / 128, (B_ * SKV_) / 128), 256>>>(ch, wv, bv, nullptr, Vh, E_, KDIM);

    // attention (fp16 in/out)
    attn_h<<<dim3(SQ_ / 128, H_, B_), 256, ATTN_SMEM>>>(Qh, Kh, Vh, AOh);

    // vocab projection (fp32 out)
    gemm_h<<<dim3(VOC_ / 128, (B_ * SQ_) / 128), 256>>>(AOh, wp, bp, out, nullptr, VOC_, KDIM);
}

// round 6
// speedup vs baseline: 7.3985x; 1.2186x over previous
#include <cuda_runtime.h>
#include <cuda_fp16.h>
#include <cstdint>

#define B_   2
#define SQ_  1024
#define SKV_ 2048
#define E_   1024
#define H_   16
#define VOC_ 4096
#define KDIM 1024

// ---------------------------------------------------------------------------
// Static scratch
// ---------------------------------------------------------------------------
__device__ __half g_Qh [B_*SQ_ *E_];
__device__ __half g_Kh [B_*SKV_*E_];
__device__ __half g_Vh [B_*SKV_*E_];
__device__ __half g_AOh[B_*SQ_ *E_];
__device__ __half g_xh [B_*SQ_ *E_];
__device__ __half g_ch [B_*SKV_*E_];
__device__ __half g_Wqh[E_*E_];
__device__ __half g_Wkh[E_*E_];
__device__ __half g_Wvh[E_*E_];
__device__ __half g_Wph[(size_t)E_*VOC_];

// ---------------------------------------------------------------------------
// PTX helpers (baseline PTX only — compiles for compute_103)
// ---------------------------------------------------------------------------
__device__ __forceinline__ uint32_t smem_u32(const void* p) {
    uint32_t a;
    asm("{ .reg .u64 t; cvta.to.shared.u64 t, %1; cvt.u32.u64 %0, t; }"
        : "=r"(a) : "l"(p));
    return a;
}

#define CP16(s, g) \
    asm volatile("cp.async.cg.shared.global [%0], [%1], 16;" :: "r"(s), "l"(g))
#define CP_COMMIT() asm volatile("cp.async.commit_group;" ::: "memory")
#define CP_WAIT0()  asm volatile("cp.async.wait_group 0;" ::: "memory")
#define CP_WAIT1()  asm volatile("cp.async.wait_group 1;" ::: "memory")

#define LDSM4(d0, d1, d2, d3, a)                                              \
    asm volatile("ldmatrix.sync.aligned.m8n8.x4.shared.b16 {%0,%1,%2,%3}, [%4];" \
        : "=r"(d0), "=r"(d1), "=r"(d2), "=r"(d3) : "r"(a))
#define LDSM4T(d0, d1, d2, d3, a)                                             \
    asm volatile("ldmatrix.sync.aligned.m8n8.x4.trans.shared.b16 {%0,%1,%2,%3}, [%4];" \
        : "=r"(d0), "=r"(d1), "=r"(d2), "=r"(d3) : "r"(a))

#define MMA16816(c, a, b0, b1)                                                \
    asm volatile("mma.sync.aligned.m16n8k16.row.col.f32.f16.f16.f32 "         \
        "{%0,%1,%2,%3},{%4,%5,%6,%7},{%8,%9},{%0,%1,%2,%3};"                  \
        : "+f"((c)[0]), "+f"((c)[1]), "+f"((c)[2]), "+f"((c)[3])              \
        : "r"((a)[0]), "r"((a)[1]), "r"((a)[2]), "r"((a)[3]), "r"(b0), "r"(b1))

__device__ __forceinline__ uint32_t packh2(float x, float y) {
    __half2 h = __floats2half2_rn(x, y);
    return *reinterpret_cast<uint32_t*>(&h);
}

// ---------------------------------------------------------------------------
// fp32 -> fp16 streaming conversion
// ---------------------------------------------------------------------------
__global__ void f2h_kernel(const float* __restrict__ in,
                           __half* __restrict__ out, int n)
{
    int i = (blockIdx.x * blockDim.x + threadIdx.x) * 4;
    if (i >= n) return;
    float4 v = *(const float4*)(in + i);
    *(__half2*)(out + i)     = __floats2half2_rn(v.x, v.y);
    *(__half2*)(out + i + 2) = __floats2half2_rn(v.z, v.w);
}

// ---------------------------------------------------------------------------
// fp16 tensor-core GEMM: C[M,N] = A[M,K] @ W[K,N] + bias
// A row-major [M][K]; W row-major [K][N] (natural layout, no pre-transpose —
// B-fragments come from ldmatrix.trans). 128x128x32 tiles, 256 threads,
// 3-stage cp.async pipeline with ONE __syncthreads per K-iteration.
// Cf != nullptr -> fp32 out; else fp16 to Ch.
// ---------------------------------------------------------------------------
#define GS   40          // A smem row stride (halves): 32 + 8 pad = 80B
#define BSS  136         // B smem row stride (halves): 128 + 8 pad = 272B
#define A_STG (128 * GS * 2)
#define B_STG (32 * BSS * 2)
#define GEMM_SMEM (3 * (A_STG + B_STG))

__global__ __launch_bounds__(256)
void gemm_h(const __half* __restrict__ A, const __half* __restrict__ W,
            const float* __restrict__ bias, float* __restrict__ Cf,
            __half* __restrict__ Ch, int N, int K)
{
    extern __shared__ __align__(16) char gsm[];
    __half* As = (__half*)gsm;                    // 3 stages, A_STG each
    __half* Bs = (__half*)(gsm + 3 * A_STG);      // 3 stages, B_STG each

    const int tid = threadIdx.x;
    const int lane = tid & 31, wid = tid >> 5;
    const int wm = wid & 3, wn = wid >> 2;        // 4x2 warp grid
    const int rowBase = blockIdx.y * 128, colBase = blockIdx.x * 128;

    // A loader: 128 rows x 4 segs(16B) = 512 chunks, 2/thread
    const __half* Aga[2]; uint32_t sAa[2];
#pragma unroll
    for (int i = 0; i < 2; i++) {
        const int idx = tid + i * 256;
        const int row = idx >> 2, seg = idx & 3;
        Aga[i] = A + (size_t)(rowBase + row) * K + seg * 8;
        sAa[i] = smem_u32(As + row * GS + seg * 8);
    }
    // B loader: 32 k-rows x 16 segs(16B) = 512 chunks, 2/thread
    const __half* Bga[2]; uint32_t sBa[2];
#pragma unroll
    for (int i = 0; i < 2; i++) {
        const int idx = tid + i * 256;
        const int row = idx >> 4, seg = idx & 15;
        Bga[i] = W + (size_t)row * N + colBase + seg * 8;
        sBa[i] = smem_u32(Bs + row * BSS + seg * 8);
    }

    auto issue = [&](int st, int it) {
        const int kk = it * 32;
        const size_t koff = (size_t)kk * N;
#pragma unroll
        for (int i = 0; i < 2; i++) {
            CP16(sAa[i] + st * A_STG, Aga[i] + kk);
            CP16(sBa[i] + st * B_STG, Bga[i] + koff);
        }
        CP_COMMIT();
    };

    // fragment base addresses
    const uint32_t aAddr = smem_u32(As + (wm * 32 + (lane & 15)) * GS + (lane >> 4) * 8);
    const int g = lane >> 3;
    const uint32_t bAddr = smem_u32(Bs + ((g & 1) * 8 + (lane & 7)) * BSS
                                       + wn * 64 + (g >> 1) * 8);

    float acc[2][8][4];
#pragma unroll
    for (int i = 0; i < 2; i++)
#pragma unroll
        for (int j = 0; j < 8; j++)
#pragma unroll
            for (int q = 0; q < 4; q++) acc[i][j][q] = 0.f;

    issue(0, 0);
    issue(1, 1);

    const int NIT = K >> 5;
    int st = 0, st2 = 2;                          // it%3, (it+2)%3
    for (int it = 0; it < NIT; it++) {
        if (it < NIT - 1) CP_WAIT1(); else CP_WAIT0();
        __syncthreads();

        const uint32_t ao = st * A_STG, bo = st * B_STG;
#pragma unroll
        for (int ks = 0; ks < 2; ks++) {
            uint32_t a[2][4];
#pragma unroll
            for (int mt = 0; mt < 2; mt++)
                LDSM4(a[mt][0], a[mt][1], a[mt][2], a[mt][3],
                      aAddr + ao + (mt * 16 * GS + ks * 16) * 2);
#pragma unroll
            for (int np = 0; np < 4; np++) {
                uint32_t d0, d1, d2, d3;
                LDSM4T(d0, d1, d2, d3,
                       bAddr + bo + (ks * 16 * BSS + np * 16) * 2);
#pragma unroll
                for (int mt = 0; mt < 2; mt++) {
                    MMA16816(acc[mt][np * 2],     a[mt], d0, d1);
                    MMA16816(acc[mt][np * 2 + 1], a[mt], d2, d3);
                }
            }
        }

        if (it + 2 < NIT) issue(st2, it + 2);
        st  = (st  == 2) ? 0 : st  + 1;
        st2 = (st2 == 2) ? 0 : st2 + 1;
    }

    // epilogue
    const int r0 = rowBase + wm * 32 + (lane >> 2);
    const int c0 = colBase + wn * 64 + (lane & 3) * 2;
#pragma unroll
    for (int mt = 0; mt < 2; mt++)
#pragma unroll
        for (int nt = 0; nt < 8; nt++) {
            const int c = c0 + nt * 8;
            const float bx = bias[c], by = bias[c + 1];
#pragma unroll
            for (int rr = 0; rr < 2; rr++) {
                const int r = r0 + mt * 16 + rr * 8;
                const float vx = acc[mt][nt][rr * 2]     + bx;
                const float vy = acc[mt][nt][rr * 2 + 1] + by;
                if (Cf) {
                    float2 o; o.x = vx; o.y = vy;
                    *(float2*)(Cf + (size_t)r * N + c) = o;
                } else {
                    *(__half2*)(Ch + (size_t)r * N + c) = __floats2half2_rn(vx, vy);
                }
            }
        }
}

// ---------------------------------------------------------------------------
// fp16 flash attention (unchanged from round 5): CTA = (128-q tile, head, b).
// ---------------------------------------------------------------------------
#define AS 72   // attention smem row stride in halves (64 + 8 pad = 144B)
#define ATTN_SMEM ((128 * AS + 4 * 64 * AS) * 2)

__global__ __launch_bounds__(256)
void attn_h(const __half* __restrict__ Q, const __half* __restrict__ K,
            const __half* __restrict__ V, __half* __restrict__ O)
{
    extern __shared__ __align__(16) __half sh[];
    __half* Qs = sh;                       // 128*72
    __half* Ks = sh + 128 * AS;            // 2 stages of 64*72
    __half* Vs = Ks + 2 * 64 * AS;

    const int tid = threadIdx.x, lane = tid & 31, wid = tid >> 5;
    const int qt = blockIdx.x, h = blockIdx.y, b = blockIdx.z;

    const __half* Qg = Q + ((size_t)b * SQ_ + qt * 128) * E_ + h * 64;
#pragma unroll
    for (int i = 0; i < 4; i++) {
        int idx = tid + i * 256;           // 0..1023
        int row = idx >> 3, seg = idx & 7;
        *(uint4*)(Qs + row * AS + seg * 8) =
            *(const uint4*)(Qg + (size_t)row * E_ + seg * 8);
    }

    const __half* Kg0 = K + (size_t)b * SKV_ * E_ + h * 64;
    const __half* Vg0 = V + (size_t)b * SKV_ * E_ + h * 64;
    const uint32_t ksb = smem_u32(Ks), vsb = smem_u32(Vs);
    const uint32_t KSTG = 64 * AS * 2;

    auto issue = [&](int st, int c) {
        const __half* Kg = Kg0 + (size_t)c * 64 * E_;
        const __half* Vg = Vg0 + (size_t)c * 64 * E_;
#pragma unroll
        for (int i = 0; i < 2; i++) {
            int idx = tid + i * 256;       // 0..511
            int row = idx >> 3, seg = idx & 7;
            uint32_t so = st * KSTG + (row * AS + seg * 8) * 2;
            CP16(ksb + so, Kg + (size_t)row * E_ + seg * 8);
            CP16(vsb + so, Vg + (size_t)row * E_ + seg * 8);
        }
        CP_COMMIT();
    };

    issue(0, 0);

    float m2[2] = { -1e30f, -1e30f };
    float ls[2] = { 0.f, 0.f };
    float o[8][4];
#pragma unroll
    for (int i = 0; i < 8; i++)
#pragma unroll
        for (int j = 0; j < 4; j++) o[i][j] = 0.f;

    const uint32_t qAddr = smem_u32(Qs + (wid * 16 + (lane & 15)) * AS + (lane >> 4) * 8);
    const float c2 = 0.125f * 1.44269504089f;   // scale * log2(e)

    for (int c = 0; c < SKV_ / 64; c++) {
        if (c + 1 < SKV_ / 64) { issue((c + 1) & 1, c + 1); CP_WAIT1(); }
        else                   { CP_WAIT0(); }
        __syncthreads();
        const uint32_t so = (c & 1) * KSTG;

        // ---- S = Q @ K^T  (16 x 64 per warp)
        float sacc[8][4];
#pragma unroll
        for (int i = 0; i < 8; i++)
#pragma unroll
            for (int j = 0; j < 4; j++) sacc[i][j] = 0.f;

#pragma unroll
        for (int ks = 0; ks < 4; ks++) {
            uint32_t a[4];
            LDSM4(a[0], a[1], a[2], a[3], qAddr + ks * 32);
#pragma unroll
            for (int np = 0; np < 4; np++) {
                uint32_t d0, d1, d2, d3;
                LDSM4(d0, d1, d2, d3,
                      ksb + so + ((np * 16 + (lane & 15)) * AS + ks * 16 + (lane >> 4) * 8) * 2);
                MMA16816(sacc[np * 2],     a, d0, d2);
                MMA16816(sacc[np * 2 + 1], a, d1, d3);
            }
        }

        // ---- online softmax (base-2)
#pragma unroll
        for (int i = 0; i < 8; i++)
#pragma unroll
            for (int j = 0; j < 4; j++) sacc[i][j] *= c2;

#pragma unroll
        for (int rr = 0; rr < 2; rr++) {
            float mx = -1e30f;
#pragma unroll
            for (int nt = 0; nt < 8; nt++)
                mx = fmaxf(mx, fmaxf(sacc[nt][rr * 2], sacc[nt][rr * 2 + 1]));
            mx = fmaxf(mx, __shfl_xor_sync(0xffffffffu, mx, 1));
            mx = fmaxf(mx, __shfl_xor_sync(0xffffffffu, mx, 2));
            const float mn = fmaxf(m2[rr], mx);
            const float al = exp2f(m2[rr] - mn);
            float rs = 0.f;
#pragma unroll
            for (int nt = 0; nt < 8; nt++) {
                sacc[nt][rr * 2]     = exp2f(sacc[nt][rr * 2]     - mn);
                sacc[nt][rr * 2 + 1] = exp2f(sacc[nt][rr * 2 + 1] - mn);
                rs += sacc[nt][rr * 2] + sacc[nt][rr * 2 + 1];
            }
            rs += __shfl_xor_sync(0xffffffffu, rs, 1);
            rs += __shfl_xor_sync(0xffffffffu, rs, 2);
            ls[rr] = ls[rr] * al + rs;
            m2[rr] = mn;
#pragma unroll
            for (int nt = 0; nt < 8; nt++) {
                o[nt][rr * 2]     *= al;
                o[nt][rr * 2 + 1] *= al;
            }
        }

        // ---- O += P @ V  (P fragments built in-register from sacc)
        const int g = lane >> 3;
#pragma unroll
        for (int t = 0; t < 4; t++) {
            uint32_t pa[4];
            pa[0] = packh2(sacc[2 * t][0],     sacc[2 * t][1]);
            pa[1] = packh2(sacc[2 * t][2],     sacc[2 * t][3]);
            pa[2] = packh2(sacc[2 * t + 1][0], sacc[2 * t + 1][1]);
            pa[3] = packh2(sacc[2 * t + 1][2], sacc[2 * t + 1][3]);
#pragma unroll
            for (int np = 0; np < 4; np++) {
                uint32_t d0, d1, d2, d3;
                uint32_t va = vsb + so +
                    ((t * 16 + (g & 1) * 8 + (lane & 7)) * AS + np * 16 + (g >> 1) * 8) * 2;
                LDSM4T(d0, d1, d2, d3, va);
                MMA16816(o[np * 2],     pa, d0, d1);
                MMA16816(o[np * 2 + 1], pa, d2, d3);
            }
        }
        __syncthreads();
    }

    // ---- epilogue: normalize, fp16 store
#pragma unroll
    for (int rr = 0; rr < 2; rr++) {
        const float inv = 1.f / ls[rr];
        const int row = qt * 128 + wid * 16 + (lane >> 2) + rr * 8;
        const size_t base = ((size_t)b * SQ_ + row) * E_ + h * 64 + (lane & 3) * 2;
#pragma unroll
        for (int nt = 0; nt < 8; nt++)
            *(__half2*)(O + base + nt * 8) =
                __floats2half2_rn(o[nt][rr * 2] * inv, o[nt][rr * 2 + 1] * inv);
    }
}

// ---------------------------------------------------------------------------
// Launch
// ---------------------------------------------------------------------------
extern "C" void kernel_launch(void* const* d_in, const int* in_sizes, int n_in,
                              void* d_out, int out_size)
{
    (void)in_sizes; (void)n_in; (void)out_size;
    const float* x   = (const float*)d_in[0];
    const float* ctx = (const float*)d_in[1];
    const float* Wq  = (const float*)d_in[2];
    const float* bq  = (const float*)d_in[3];
    const float* Wk  = (const float*)d_in[4];
    const float* bk  = (const float*)d_in[5];
    const float* Wv  = (const float*)d_in[6];
    const float* bv  = (const float*)d_in[7];
    const float* Wp  = (const float*)d_in[8];
    const float* bp  = (const float*)d_in[9];
    float* out = (float*)d_out;

    __half *Qh, *Kh, *Vh, *AOh, *xh, *ch, *wq, *wk, *wv, *wp;
    cudaGetSymbolAddress((void**)&Qh,  g_Qh);
    cudaGetSymbolAddress((void**)&Kh,  g_Kh);
    cudaGetSymbolAddress((void**)&Vh,  g_Vh);
    cudaGetSymbolAddress((void**)&AOh, g_AOh);
    cudaGetSymbolAddress((void**)&xh,  g_xh);
    cudaGetSymbolAddress((void**)&ch,  g_ch);
    cudaGetSymbolAddress((void**)&wq,  g_Wqh);
    cudaGetSymbolAddress((void**)&wk,  g_Wkh);
    cudaGetSymbolAddress((void**)&wv,  g_Wvh);
    cudaGetSymbolAddress((void**)&wp,  g_Wph);

    cudaFuncSetAttribute(attn_h, cudaFuncAttributeMaxDynamicSharedMemorySize, ATTN_SMEM);
    cudaFuncSetAttribute(gemm_h, cudaFuncAttributeMaxDynamicSharedMemorySize, GEMM_SMEM);

    // fp32 -> fp16 conversions (pure streaming, no transposes)
    f2h_kernel<<<B_ * SQ_ * E_  / 4 / 256, 256>>>(x,   xh, B_ * SQ_ * E_);
    f2h_kernel<<<B_ * SKV_ * E_ / 4 / 256, 256>>>(ctx, ch, B_ * SKV_ * E_);
    f2h_kernel<<<E_ * E_   / 4 / 256, 256>>>(Wq, wq, E_ * E_);
    f2h_kernel<<<E_ * E_   / 4 / 256, 256>>>(Wk, wk, E_ * E_);
    f2h_kernel<<<E_ * E_   / 4 / 256, 256>>>(Wv, wv, E_ * E_);
    f2h_kernel<<<E_ * VOC_ / 4 / 256, 256>>>(Wp, wp, E_ * VOC_);

    // QKV projections (fp16 out)
    gemm_h<<<dim3(E_ / 128, (B_ * SQ_)  / 128), 256, GEMM_SMEM>>>(xh, wq, bq, nullptr, Qh, E_, KDIM);
    gemm_h<<<dim3(E_ / 128, (B_ * SKV_) / 128), 256, GEMM_SMEM>>>(ch, wk, bk, nullptr, Kh, E_, KDIM);
    gemm_h<<<dim3(E_ / 128, (B_ * SKV_) / 128), 256, GEMM_SMEM>>>(ch, wv, bv, nullptr, Vh, E_, KDIM);

    // attention (fp16 in/out)
    attn_h<<<dim3(SQ_ / 128, H_, B_), 256, ATTN_SMEM>>>(Qh, Kh, Vh, AOh);

    // vocab projection (fp32 out)
    gemm_h<<<dim3(VOC_ / 128, (B_ * SQ_) / 128), 256, GEMM_SMEM>>>(AOh, wp, bp, out, nullptr, VOC_, KDIM);
}

// round 7
// speedup vs baseline: 7.7808x; 1.0517x over previous
#include <cuda_runtime.h>
#include <cuda_fp16.h>
#include <cstdint>

#define B_   2
#define SQ_  1024
#define SKV_ 2048
#define E_   1024
#define H_   16
#define VOC_ 4096
#define KDIM 1024

// ---------------------------------------------------------------------------
// Static scratch
// ---------------------------------------------------------------------------
__device__ __half g_Qh [B_*SQ_ *E_];
__device__ __half g_Kh [B_*SKV_*E_];
__device__ __half g_Vh [B_*SKV_*E_];
__device__ __half g_AOh[B_*SQ_ *E_];
__device__ __half g_xh [B_*SQ_ *E_];
__device__ __half g_ch [B_*SKV_*E_];
__device__ __half g_Wqh[E_*E_];
__device__ __half g_Wkh[E_*E_];
__device__ __half g_Wvh[E_*E_];
__device__ __half g_Wph[(size_t)E_*VOC_];

// ---------------------------------------------------------------------------
// PTX helpers (baseline PTX only — compiles for compute_103)
// ---------------------------------------------------------------------------
__device__ __forceinline__ uint32_t smem_u32(const void* p) {
    uint32_t a;
    asm("{ .reg .u64 t; cvta.to.shared.u64 t, %1; cvt.u32.u64 %0, t; }"
        : "=r"(a) : "l"(p));
    return a;
}

#define CP16(s, g) \
    asm volatile("cp.async.cg.shared.global [%0], [%1], 16;" :: "r"(s), "l"(g))
#define CP_COMMIT() asm volatile("cp.async.commit_group;" ::: "memory")
#define CP_WAIT0()  asm volatile("cp.async.wait_group 0;" ::: "memory")
#define CP_WAIT1()  asm volatile("cp.async.wait_group 1;" ::: "memory")

#define LDSM4(d0, d1, d2, d3, a)                                              \
    asm volatile("ldmatrix.sync.aligned.m8n8.x4.shared.b16 {%0,%1,%2,%3}, [%4];" \
        : "=r"(d0), "=r"(d1), "=r"(d2), "=r"(d3) : "r"(a))
#define LDSM4T(d0, d1, d2, d3, a)                                             \
    asm volatile("ldmatrix.sync.aligned.m8n8.x4.trans.shared.b16 {%0,%1,%2,%3}, [%4];" \
        : "=r"(d0), "=r"(d1), "=r"(d2), "=r"(d3) : "r"(a))

#define MMA16816(c, a, b0, b1)                                                \
    asm volatile("mma.sync.aligned.m16n8k16.row.col.f32.f16.f16.f32 "         \
        "{%0,%1,%2,%3},{%4,%5,%6,%7},{%8,%9},{%0,%1,%2,%3};"                  \
        : "+f"((c)[0]), "+f"((c)[1]), "+f"((c)[2]), "+f"((c)[3])              \
        : "r"((a)[0]), "r"((a)[1]), "r"((a)[2]), "r"((a)[3]), "r"(b0), "r"(b1))

__device__ __forceinline__ uint32_t packh2(float x, float y) {
    __half2 h = __floats2half2_rn(x, y);
    return *reinterpret_cast<uint32_t*>(&h);
}

// ---------------------------------------------------------------------------
// Fused fp32 -> fp16 conversion for ALL tensors in ONE launch.
// Block segments (1024 elements each):
//   x  : [0,     2048)   ctx: [2048,  6144)  Wq: [6144, 7168)
//   Wk : [7168,  8192)   Wv : [8192,  9216)  Wp: [9216, 13312)
// ---------------------------------------------------------------------------
#define F2H_BLOCKS 13312

__global__ __launch_bounds__(256)
void f2h_all(const float* __restrict__ x,   const float* __restrict__ ctx,
             const float* __restrict__ wq,  const float* __restrict__ wk,
             const float* __restrict__ wv,  const float* __restrict__ wp,
             __half* xh, __half* ch, __half* wqh,
             __half* wkh, __half* wvh, __half* wph)
{
    const int bb = blockIdx.x;
    const float* in; __half* out; int base;
    if      (bb < 2048) { in = x;   out = xh;  base = bb;        }
    else if (bb < 6144) { in = ctx; out = ch;  base = bb - 2048; }
    else if (bb < 7168) { in = wq;  out = wqh; base = bb - 6144; }
    else if (bb < 8192) { in = wk;  out = wkh; base = bb - 7168; }
    else if (bb < 9216) { in = wv;  out = wvh; base = bb - 8192; }
    else                { in = wp;  out = wph; base = bb - 9216; }
    const size_t i = (size_t)base * 1024 + threadIdx.x * 4;
    float4 v = *(const float4*)(in + i);
    *(__half2*)(out + i)     = __floats2half2_rn(v.x, v.y);
    *(__half2*)(out + i + 2) = __floats2half2_rn(v.z, v.w);
}

// ---------------------------------------------------------------------------
// fp16 tensor-core GEMM body: C[M,N] = A[M,K] @ W[K,N] + bias
// A row-major [M][K]; W row-major [K][N] (B-fragments via ldmatrix.trans).
// 128x128x32 tiles, 256 threads, 3-stage cp.async, ONE sync per K-iteration.
// ---------------------------------------------------------------------------
#define GS   40          // A smem row stride (halves): 32 + 8 pad = 80B
#define BSS  136         // B smem row stride (halves): 128 + 8 pad = 272B
#define A_STG (128 * GS * 2)
#define B_STG (32 * BSS * 2)
#define GEMM_SMEM (3 * (A_STG + B_STG))

__device__ __forceinline__
void gemm_body(const __half* __restrict__ A, const __half* __restrict__ W,
               const float* __restrict__ bias, float* __restrict__ Cf,
               __half* __restrict__ Ch, int N, int K,
               int rowBase, int colBase, char* gsm)
{
    __half* As = (__half*)gsm;
    __half* Bs = (__half*)(gsm + 3 * A_STG);

    const int tid = threadIdx.x;
    const int lane = tid & 31, wid = tid >> 5;
    const int wm = wid & 3, wn = wid >> 2;        // 4x2 warp grid

    // A loader: 128 rows x 4 segs(16B) = 512 chunks, 2/thread
    const __half* Aga[2]; uint32_t sAa[2];
#pragma unroll
    for (int i = 0; i < 2; i++) {
        const int idx = tid + i * 256;
        const int row = idx >> 2, seg = idx & 3;
        Aga[i] = A + (size_t)(rowBase + row) * K + seg * 8;
        sAa[i] = smem_u32(As + row * GS + seg * 8);
    }
    // B loader: 32 k-rows x 16 segs(16B) = 512 chunks, 2/thread
    const __half* Bga[2]; uint32_t sBa[2];
#pragma unroll
    for (int i = 0; i < 2; i++) {
        const int idx = tid + i * 256;
        const int row = idx >> 4, seg = idx & 15;
        Bga[i] = W + (size_t)row * N + colBase + seg * 8;
        sBa[i] = smem_u32(Bs + row * BSS + seg * 8);
    }

    auto issue = [&](int st, int it) {
        const int kk = it * 32;
        const size_t koff = (size_t)kk * N;
#pragma unroll
        for (int i = 0; i < 2; i++) {
            CP16(sAa[i] + st * A_STG, Aga[i] + kk);
            CP16(sBa[i] + st * B_STG, Bga[i] + koff);
        }
        CP_COMMIT();
    };

    const uint32_t aAddr = smem_u32(As + (wm * 32 + (lane & 15)) * GS + (lane >> 4) * 8);
    const int g = lane >> 3;
    const uint32_t bAddr = smem_u32(Bs + ((g & 1) * 8 + (lane & 7)) * BSS
                                       + wn * 64 + (g >> 1) * 8);

    float acc[2][8][4];
#pragma unroll
    for (int i = 0; i < 2; i++)
#pragma unroll
        for (int j = 0; j < 8; j++)
#pragma unroll
            for (int q = 0; q < 4; q++) acc[i][j][q] = 0.f;

    issue(0, 0);
    issue(1, 1);

    const int NIT = K >> 5;
    int st = 0, st2 = 2;
    for (int it = 0; it < NIT; it++) {
        if (it < NIT - 1) CP_WAIT1(); else CP_WAIT0();
        __syncthreads();

        const uint32_t ao = st * A_STG, bo = st * B_STG;
#pragma unroll
        for (int ks = 0; ks < 2; ks++) {
            uint32_t a[2][4];
#pragma unroll
            for (int mt = 0; mt < 2; mt++)
                LDSM4(a[mt][0], a[mt][1], a[mt][2], a[mt][3],
                      aAddr + ao + (mt * 16 * GS + ks * 16) * 2);
#pragma unroll
            for (int np = 0; np < 4; np++) {
                uint32_t d0, d1, d2, d3;
                LDSM4T(d0, d1, d2, d3,
                       bAddr + bo + (ks * 16 * BSS + np * 16) * 2);
#pragma unroll
                for (int mt = 0; mt < 2; mt++) {
                    MMA16816(acc[mt][np * 2],     a[mt], d0, d1);
                    MMA16816(acc[mt][np * 2 + 1], a[mt], d2, d3);
                }
            }
        }

        if (it + 2 < NIT) issue(st2, it + 2);
        st  = (st  == 2) ? 0 : st  + 1;
        st2 = (st2 == 2) ? 0 : st2 + 1;
    }

    // epilogue
    const int r0 = rowBase + wm * 32 + (lane >> 2);
    const int c0 = colBase + wn * 64 + (lane & 3) * 2;
#pragma unroll
    for (int mt = 0; mt < 2; mt++)
#pragma unroll
        for (int nt = 0; nt < 8; nt++) {
            const int c = c0 + nt * 8;
            const float bx = bias[c], by = bias[c + 1];
#pragma unroll
            for (int rr = 0; rr < 2; rr++) {
                const int r = r0 + mt * 16 + rr * 8;
                const float vx = acc[mt][nt][rr * 2]     + bx;
                const float vy = acc[mt][nt][rr * 2 + 1] + by;
                if (Cf) {
                    float2 o; o.x = vx; o.y = vy;
                    *(float2*)(Cf + (size_t)r * N + c) = o;
                } else {
                    *(__half2*)(Ch + (size_t)r * N + c) = __floats2half2_rn(vx, vy);
                }
            }
        }
}

// Merged QKV projection: blockIdx.z selects {Q, K, V}.
__global__ __launch_bounds__(256)
void gemm_qkv(const __half* __restrict__ xh, const __half* __restrict__ ch,
              const __half* __restrict__ wq, const __half* __restrict__ wk,
              const __half* __restrict__ wv,
              const float* __restrict__ bq, const float* __restrict__ bk,
              const float* __restrict__ bv,
              __half* __restrict__ Qh, __half* __restrict__ Kh,
              __half* __restrict__ Vh)
{
    extern __shared__ __align__(16) char gsm[];
    const int z = blockIdx.z;
    const __half* A; const __half* W; const float* bias; __half* C; int M;
    if (z == 0)      { A = xh; W = wq; bias = bq; C = Qh; M = B_ * SQ_;  }
    else if (z == 1) { A = ch; W = wk; bias = bk; C = Kh; M = B_ * SKV_; }
    else             { A = ch; W = wv; bias = bv; C = Vh; M = B_ * SKV_; }
    const int rowBase = blockIdx.y * 128;
    if (rowBase >= M) return;
    gemm_body(A, W, bias, nullptr, C, E_, KDIM, rowBase, blockIdx.x * 128, gsm);
}

// Vocab projection (fp32 out).
__global__ __launch_bounds__(256)
void gemm_vocab(const __half* __restrict__ A, const __half* __restrict__ W,
                const float* __restrict__ bias, float* __restrict__ C)
{
    extern __shared__ __align__(16) char gsm[];
    gemm_body(A, W, bias, C, nullptr, VOC_, KDIM,
              blockIdx.y * 128, blockIdx.x * 128, gsm);
}

// ---------------------------------------------------------------------------
// fp16 flash attention: CTA = (128-q tile, head, batch), 256 thr / 8 warps.
// 3-stage cp.async K/V pipeline, ONE __syncthreads per kv-iteration.
// ---------------------------------------------------------------------------
#define AS 72   // attention smem row stride in halves (64 + 8 pad = 144B)
#define ATTN_SMEM ((128 * AS + 6 * 64 * AS) * 2)

__global__ __launch_bounds__(256)
void attn_h(const __half* __restrict__ Q, const __half* __restrict__ K,
            const __half* __restrict__ V, __half* __restrict__ O)
{
    extern __shared__ __align__(16) __half sh[];
    __half* Qs = sh;                       // 128*72
    __half* Ks = sh + 128 * AS;            // 3 stages of 64*72
    __half* Vs = Ks + 3 * 64 * AS;         // 3 stages of 64*72

    const int tid = threadIdx.x, lane = tid & 31, wid = tid >> 5;
    const int qt = blockIdx.x, h = blockIdx.y, b = blockIdx.z;

    const __half* Qg = Q + ((size_t)b * SQ_ + qt * 128) * E_ + h * 64;
#pragma unroll
    for (int i = 0; i < 4; i++) {
        int idx = tid + i * 256;           // 0..1023
        int row = idx >> 3, seg = idx & 7;
        *(uint4*)(Qs + row * AS + seg * 8) =
            *(const uint4*)(Qg + (size_t)row * E_ + seg * 8);
    }

    const __half* Kg0 = K + (size_t)b * SKV_ * E_ + h * 64;
    const __half* Vg0 = V + (size_t)b * SKV_ * E_ + h * 64;
    const uint32_t ksb = smem_u32(Ks), vsb = smem_u32(Vs);
    const uint32_t KSTG = 64 * AS * 2;

    auto issue = [&](int st, int c) {
        const __half* Kg = Kg0 + (size_t)c * 64 * E_;
        const __half* Vg = Vg0 + (size_t)c * 64 * E_;
#pragma unroll
        for (int i = 0; i < 2; i++) {
            int idx = tid + i * 256;       // 0..511
            int row = idx >> 3, seg = idx & 7;
            uint32_t so = st * KSTG + (row * AS + seg * 8) * 2;
            CP16(ksb + so, Kg + (size_t)row * E_ + seg * 8);
            CP16(vsb + so, Vg + (size_t)row * E_ + seg * 8);
        }
        CP_COMMIT();
    };

    issue(0, 0);
    issue(1, 1);

    float m2[2] = { -1e30f, -1e30f };
    float ls[2] = { 0.f, 0.f };
    float o[8][4];
#pragma unroll
    for (int i = 0; i < 8; i++)
#pragma unroll
        for (int j = 0; j < 4; j++) o[i][j] = 0.f;

    const uint32_t qAddr = smem_u32(Qs + (wid * 16 + (lane & 15)) * AS + (lane >> 4) * 8);
    const float c2 = 0.125f * 1.44269504089f;   // scale * log2(e)
    const int NKV = SKV_ / 64;

    int st = 0, st2 = 2;
    for (int c = 0; c < NKV; c++) {
        if (c < NKV - 1) CP_WAIT1(); else CP_WAIT0();
        __syncthreads();
        const uint32_t so = st * KSTG;

        // ---- S = Q @ K^T  (16 x 64 per warp)
        float sacc[8][4];
#pragma unroll
        for (int i = 0; i < 8; i++)
#pragma unroll
            for (int j = 0; j < 4; j++) sacc[i][j] = 0.f;

#pragma unroll
        for (int ks = 0; ks < 4; ks++) {
            uint32_t a[4];
            LDSM4(a[0], a[1], a[2], a[3], qAddr + ks * 32);
#pragma unroll
            for (int np = 0; np < 4; np++) {
                uint32_t d0, d1, d2, d3;
                LDSM4(d0, d1, d2, d3,
                      ksb + so + ((np * 16 + (lane & 15)) * AS + ks * 16 + (lane >> 4) * 8) * 2);
                MMA16816(sacc[np * 2],     a, d0, d2);
                MMA16816(sacc[np * 2 + 1], a, d1, d3);
            }
        }

        // ---- online softmax (base-2)
#pragma unroll
        for (int i = 0; i < 8; i++)
#pragma unroll
            for (int j = 0; j < 4; j++) sacc[i][j] *= c2;

#pragma unroll
        for (int rr = 0; rr < 2; rr++) {
            float mx = -1e30f;
#pragma unroll
            for (int nt = 0; nt < 8; nt++)
                mx = fmaxf(mx, fmaxf(sacc[nt][rr * 2], sacc[nt][rr * 2 + 1]));
            mx = fmaxf(mx, __shfl_xor_sync(0xffffffffu, mx, 1));
            mx = fmaxf(mx, __shfl_xor_sync(0xffffffffu, mx, 2));
            const float mn = fmaxf(m2[rr], mx);
            const float al = exp2f(m2[rr] - mn);
            float rs = 0.f;
#pragma unroll
            for (int nt = 0; nt < 8; nt++) {
                sacc[nt][rr * 2]     = exp2f(sacc[nt][rr * 2]     - mn);
                sacc[nt][rr * 2 + 1] = exp2f(sacc[nt][rr * 2 + 1] - mn);
                rs += sacc[nt][rr * 2] + sacc[nt][rr * 2 + 1];
            }
            rs += __shfl_xor_sync(0xffffffffu, rs, 1);
            rs += __shfl_xor_sync(0xffffffffu, rs, 2);
            ls[rr] = ls[rr] * al + rs;
            m2[rr] = mn;
#pragma unroll
            for (int nt = 0; nt < 8; nt++) {
                o[nt][rr * 2]     *= al;
                o[nt][rr * 2 + 1] *= al;
            }
        }

        // ---- O += P @ V  (P fragments built in-register from sacc)
        const int g = lane >> 3;
#pragma unroll
        for (int t = 0; t < 4; t++) {
            uint32_t pa[4];
            pa[0] = packh2(sacc[2 * t][0],     sacc[2 * t][1]);
            pa[1] = packh2(sacc[2 * t][2],     sacc[2 * t][3]);
            pa[2] = packh2(sacc[2 * t + 1][0], sacc[2 * t + 1][1]);
            pa[3] = packh2(sacc[2 * t + 1][2], sacc[2 * t + 1][3]);
#pragma unroll
            for (int np = 0; np < 4; np++) {
                uint32_t d0, d1, d2, d3;
                uint32_t va = vsb + so +
                    ((t * 16 + (g & 1) * 8 + (lane & 7)) * AS + np * 16 + (g >> 1) * 8) * 2;
                LDSM4T(d0, d1, d2, d3, va);
                MMA16816(o[np * 2],     pa, d0, d1);
                MMA16816(o[np * 2 + 1], pa, d2, d3);
            }
        }

        if (c + 2 < NKV) issue(st2, c + 2);
        st  = (st  == 2) ? 0 : st  + 1;
        st2 = (st2 == 2) ? 0 : st2 + 1;
    }

    // ---- epilogue: normalize, fp16 store
#pragma unroll
    for (int rr = 0; rr < 2; rr++) {
        const float inv = 1.f / ls[rr];
        const int row = qt * 128 + wid * 16 + (lane >> 2) + rr * 8;
        const size_t base = ((size_t)b * SQ_ + row) * E_ + h * 64 + (lane & 3) * 2;
#pragma unroll
        for (int nt = 0; nt < 8; nt++)
            *(__half2*)(O + base + nt * 8) =
                __floats2half2_rn(o[nt][rr * 2] * inv, o[nt][rr * 2 + 1] * inv);
    }
}

// ---------------------------------------------------------------------------
// Launch
// ---------------------------------------------------------------------------
extern "C" void kernel_launch(void* const* d_in, const int* in_sizes, int n_in,
                              void* d_out, int out_size)
{
    (void)in_sizes; (void)n_in; (void)out_size;
    const float* x   = (const float*)d_in[0];
    const float* ctx = (const float*)d_in[1];
    const float* Wq  = (const float*)d_in[2];
    const float* bq  = (const float*)d_in[3];
    const float* Wk  = (const float*)d_in[4];
    const float* bk  = (const float*)d_in[5];
    const float* Wv  = (const float*)d_in[6];
    const float* bv  = (const float*)d_in[7];
    const float* Wp  = (const float*)d_in[8];
    const float* bp  = (const float*)d_in[9];
    float* out = (float*)d_out;

    __half *Qh, *Kh, *Vh, *AOh, *xh, *ch, *wq, *wk, *wv, *wp;
    cudaGetSymbolAddress((void**)&Qh,  g_Qh);
    cudaGetSymbolAddress((void**)&Kh,  g_Kh);
    cudaGetSymbolAddress((void**)&Vh,  g_Vh);
    cudaGetSymbolAddress((void**)&AOh, g_AOh);
    cudaGetSymbolAddress((void**)&xh,  g_xh);
    cudaGetSymbolAddress((void**)&ch,  g_ch);
    cudaGetSymbolAddress((void**)&wq,  g_Wqh);
    cudaGetSymbolAddress((void**)&wk,  g_Wkh);
    cudaGetSymbolAddress((void**)&wv,  g_Wvh);
    cudaGetSymbolAddress((void**)&wp,  g_Wph);

    cudaFuncSetAttribute(attn_h,    cudaFuncAttributeMaxDynamicSharedMemorySize, ATTN_SMEM);
    cudaFuncSetAttribute(gemm_qkv,  cudaFuncAttributeMaxDynamicSharedMemorySize, GEMM_SMEM);
    cudaFuncSetAttribute(gemm_vocab,cudaFuncAttributeMaxDynamicSharedMemorySize, GEMM_SMEM);

    // all fp32 -> fp16 conversions, one launch
    f2h_all<<<F2H_BLOCKS, 256>>>(x, ctx, Wq, Wk, Wv, Wp,
                                 xh, ch, wq, wk, wv, wp);

    // QKV projections, one launch (z: 0=Q, 1=K, 2=V)
    gemm_qkv<<<dim3(E_ / 128, (B_ * SKV_) / 128, 3), 256, GEMM_SMEM>>>(
        xh, ch, wq, wk, wv, bq, bk, bv, Qh, Kh, Vh);

    // attention (fp16 in/out)
    attn_h<<<dim3(SQ_ / 128, H_, B_), 256, ATTN_SMEM>>>(Qh, Kh, Vh, AOh);

    // vocab projection (fp32 out)
    gemm_vocab<<<dim3(VOC_ / 128, (B_ * SQ_) / 128), 256, GEMM_SMEM>>>(AOh, wp, bp, out);
}